// round 5
// baseline (speedup 1.0000x reference)
#include <cuda_runtime.h>
#include <math.h>

// Problem shape (fixed by the reference setup_inputs)
#define NS 5        // S: num support classes
#define NQ 512      // Q: num queries
#define NT 64       // T: tokens pooled (mean)
#define NTH (NT/2)  // half split for pooling
#define ND 2048     // D: feature dim
#define ND4 (ND/4)  // 512 float4 per row
#define EPS 1e-8f

// Scratch (no allocations allowed in kernel_launch)
__device__ float g_sph[2][NS * ND];    // per-half raw support sums [2][S, D]
__device__ float g_qph[2][NQ * ND];    // per-half raw query sums   [2][Q, D]
__device__ float g_dist[NQ * NS];      // cosine sim [Q, S]
__device__ int   g_scnt = 0;           // supp halves completed (0..10)
__device__ int   g_qcnt[NQ] = {0};     // per-query halves completed (0..2)

__device__ __forceinline__ float4 f4add(float4 a, float4 b) {
    a.x += b.x; a.y += b.y; a.z += b.z; a.w += b.w; return a;
}
__device__ __forceinline__ float f4dot(float4 a, float4 b) {
    return a.x * b.x + a.y * b.y + a.z * b.z + a.w * b.w;
}
__device__ __forceinline__ float warp_sum(float v) {
    #pragma unroll
    for (int o = 16; o > 0; o >>= 1) v += __shfl_xor_sync(0xffffffffu, v, o);
    return v;
}

// ─── Fused kernel: stream-pool supp+query AND compute dist inline ──────────
// grid = 2*NS + 2*NQ = 1034 blocks, block = 256. Every CTA pools 32 rows x
// 2048 floats (256 KB) -> one balanced resident wave.
//   bid < 2*NS : supp row (bid>>1), half (bid&1) -> g_sph, signal g_scnt
//   else       : query row q, half. Write raw sums; SECOND finisher for q
//                combines halves + support (from L2) and emits dist.
// NOTE: cosine sim is scale-invariant, so raw sums are used throughout
// (no 1/NT scaling); the EPS clamp is inactive for both scalings here.
__global__ void __launch_bounds__(256, 7)
fused_kernel(const float* __restrict__ supp,
             const float* __restrict__ query,
             float* __restrict__ out_dist) {
    const int bid = blockIdx.x;
    const int tid = threadIdx.x;
    const bool is_supp = (bid < 2 * NS);

    int q = 0, half, s = 0;
    const float* src;
    float* dst;
    if (is_supp) {
        s = bid >> 1; half = bid & 1;
        src = supp + ((size_t)s * NT + (size_t)half * NTH) * ND;
        dst = &g_sph[half][(size_t)s * ND];
    } else {
        const int i = bid - 2 * NS;
        q = i >> 1; half = i & 1;
        src = query + ((size_t)q * NT + (size_t)half * NTH) * ND;
        dst = &g_qph[half][(size_t)q * ND];
    }

    // ── streaming half-pool: 32 rows x 8 KB, fully coalesced float4 ──
    const float4* base = reinterpret_cast<const float4*>(src);
    float4 acc0 = make_float4(0.f, 0.f, 0.f, 0.f);
    float4 acc1 = make_float4(0.f, 0.f, 0.f, 0.f);
    #pragma unroll 8
    for (int t = 0; t < NTH; t++) {
        const float4* row = base + (size_t)t * ND4;
        acc0 = f4add(acc0, row[tid]);
        acc1 = f4add(acc1, row[tid + 256]);
    }
    float4* d4 = reinterpret_cast<float4*>(dst);
    d4[tid] = acc0;          // raw sums
    d4[tid + 256] = acc1;

    // release: data visible before the arrival signal
    __threadfence();
    __syncthreads();

    __shared__ int s_old;
    if (is_supp) {
        if (tid == 0) atomicAdd(&g_scnt, 1);
        return;
    }
    if (tid == 0) s_old = atomicAdd(&g_qcnt[q], 1);
    __syncthreads();
    if (s_old == 0) return;   // first arriver exits; partner finishes q

    // ── finisher path (runs on 512 CTAs, all traffic L2-resident) ──
    // acquire supp halves (bids 0-9 complete long before any finisher)
    while (*(volatile int*)&g_scnt < 2 * NS) { }
    __threadfence();

    // combine with partner's raw half-sums (8 KB from L2)
    const float4* p4 =
        reinterpret_cast<const float4*>(&g_qph[half ^ 1][(size_t)q * ND]);
    acc0 = f4add(acc0, p4[tid]);
    acc1 = f4add(acc1, p4[tid + 256]);

    // 11 block reductions: 5 dot(q,s), 5 ||s||^2, 1 ||q||^2
    float part[11];
    part[10] = f4dot(acc0, acc0) + f4dot(acc1, acc1);
    #pragma unroll
    for (int j = 0; j < NS; j++) {
        const float4* s0 = reinterpret_cast<const float4*>(&g_sph[0][(size_t)j * ND]);
        const float4* s1 = reinterpret_cast<const float4*>(&g_sph[1][(size_t)j * ND]);
        float4 sp0 = f4add(__ldg(&s0[tid]),       __ldg(&s1[tid]));
        float4 sp1 = f4add(__ldg(&s0[tid + 256]), __ldg(&s1[tid + 256]));
        part[j]      = f4dot(acc0, sp0) + f4dot(acc1, sp1);
        part[5 + j]  = f4dot(sp0, sp0) + f4dot(sp1, sp1);
    }

    __shared__ float red[8][11];
    const int wid = tid >> 5;
    #pragma unroll
    for (int j = 0; j < 11; j++) {
        float v = warp_sum(part[j]);
        if ((tid & 31) == 0) red[wid][j] = v;
    }
    __syncthreads();

    if (tid == 0) {
        float tot[11];
        #pragma unroll
        for (int j = 0; j < 11; j++) {
            float t2 = 0.f;
            #pragma unroll
            for (int w = 0; w < 8; w++) t2 += red[w][j];
            tot[j] = t2;
        }
        const float qn = sqrtf(tot[10]);
        #pragma unroll
        for (int j = 0; j < NS; j++) {
            float denom = fmaxf(qn * sqrtf(tot[5 + j]), EPS);
            float d = tot[j] / denom;
            g_dist[q * NS + j] = d;
            out_dist[q * NS + j] = 1.0f - d;
        }
    }
}

// ─── Loss kernel: cross-entropy + counter reset for next graph replay ──────
__global__ void loss_kernel(const int* __restrict__ ys32,
                            float* __restrict__ out, int write_loss) {
    __shared__ int s_is64;
    __shared__ float red[16];
    const int tid = threadIdx.x;

    // reset arrival counters for the next launch of fused_kernel
    g_qcnt[tid] = 0;
    if (tid == 0) g_scnt = 0;

    if (tid == 0) {
        // Detect int64 vs int32 labels (values < 5; int64 high words are 0).
        int f = 1;
        for (int i = 1; i < NQ; i += 2) {
            if (ys32[i] != 0) { f = 0; break; }
        }
        s_is64 = f;
    }
    __syncthreads();

    const int y = s_is64 ? ys32[2 * tid] : ys32[tid];

    float d[NS];
    #pragma unroll
    for (int s = 0; s < NS; s++) d[s] = g_dist[tid * NS + s];
    float m = d[0];
    #pragma unroll
    for (int s = 1; s < NS; s++) m = fmaxf(m, d[s]);
    float se = 0.f;
    #pragma unroll
    for (int s = 0; s < NS; s++) se += __expf(d[s] - m);
    const float lse = m + logf(se);
    float nlp = -(d[y] - lse);

    nlp = warp_sum(nlp);
    if ((tid & 31) == 0) red[tid >> 5] = nlp;
    __syncthreads();
    if (tid == 0 && write_loss) {
        float tot = 0.f;
        #pragma unroll
        for (int w = 0; w < 16; w++) tot += red[w];
        out[0] = tot * (1.0f / (float)NQ);
    }
}

extern "C" void kernel_launch(void* const* d_in, const int* in_sizes, int n_in,
                              void* d_out, int out_size) {
    const float* supp  = (const float*)d_in[0];
    const float* query = (const float*)d_in[1];
    const int*   ys    = (const int*)d_in[2];
    if (n_in >= 2 && in_sizes[0] > in_sizes[1]) {
        const float* t = supp; supp = query; query = t;
    }
    float* out = (float*)d_out;

    const int dist_off = (out_size > NQ * NS) ? (out_size - NQ * NS) : 0;
    const int write_loss = (out_size > NQ * NS) ? 1 : 0;

    fused_kernel<<<2 * NS + 2 * NQ, 256>>>(supp, query, out + dist_off);
    loss_kernel<<<1, NQ>>>(ys, out, write_loss);
}

// round 6
// speedup vs baseline: 1.0299x; 1.0299x over previous
#include <cuda_runtime.h>
#include <math.h>

// Problem shape (fixed by the reference setup_inputs)
#define NS 5        // S: num support classes
#define NQ 512      // Q: num queries
#define NT 64       // T: tokens pooled (mean)
#define NTH (NT/2)  // half split for pooling
#define ND 2048     // D: feature dim
#define ND4 (ND/4)  // 512 float4 per row
#define EPS 1e-8f

// Scratch (no allocations allowed in kernel_launch)
__device__ float g_sph[2][NS * ND];    // per-half raw support sums [2][S, D]
__device__ float g_qph[2][NQ * ND];    // per-half raw query sums   [2][Q, D]
__device__ float g_dist[NQ * NS];      // cosine sim [Q, S]
__device__ int   g_done = 0;           // dist blocks completed (self-resetting)

__device__ __forceinline__ float4 f4add(float4 a, float4 b) {
    a.x += b.x; a.y += b.y; a.z += b.z; a.w += b.w; return a;
}
__device__ __forceinline__ float f4dot(float4 a, float4 b) {
    return a.x * b.x + a.y * b.y + a.z * b.z + a.w * b.w;
}
__device__ __forceinline__ float warp_sum(float v) {
    #pragma unroll
    for (int o = 16; o > 0; o >>= 1) v += __shfl_xor_sync(0xffffffffu, v, o);
    return v;
}

// ─── Kernel A: ONE uniform streaming pass over supp AND query ──────────────
// grid = 2*NS + 2*NQ = 1034 blocks, block = 256. Every CTA pools exactly
// 32 rows x 2048 floats (256 KB) of raw sums -> single balanced wave.
// Cosine sim is scale-invariant -> raw sums, no 1/NT scaling anywhere.
__global__ void __launch_bounds__(256, 8)
pool_all_kernel(const float* __restrict__ supp,
                const float* __restrict__ query) {
    const int bid = blockIdx.x;
    const int tid = threadIdx.x;

    const float* src;
    float* dst;
    if (bid < 2 * NS) {
        const int s = bid >> 1, half = bid & 1;
        src = supp + ((size_t)s * NT + (size_t)half * NTH) * ND;
        dst = &g_sph[half][(size_t)s * ND];
    } else {
        const int i = bid - 2 * NS;
        const int q = i >> 1, half = i & 1;
        src = query + ((size_t)q * NT + (size_t)half * NTH) * ND;
        dst = &g_qph[half][(size_t)q * ND];
    }

    const float4* base = reinterpret_cast<const float4*>(src);
    float4 acc0 = make_float4(0.f, 0.f, 0.f, 0.f);
    float4 acc1 = make_float4(0.f, 0.f, 0.f, 0.f);
    #pragma unroll 8
    for (int t = 0; t < NTH; t++) {
        const float4* row = base + (size_t)t * ND4;
        acc0 = f4add(acc0, row[tid]);
        acc1 = f4add(acc1, row[tid + 256]);
    }
    float4* d4 = reinterpret_cast<float4*>(dst);
    d4[tid] = acc0;          // raw sums
    d4[tid + 256] = acc1;
}

// ─── Kernel B: dist + (last block) cross-entropy loss ──────────────────────
// grid = NQ, block = 256. All reads L2-resident (8.1 MB scratch).
__global__ void __launch_bounds__(256, 8)
dist_loss_kernel(const int* __restrict__ ys32,
                 float* __restrict__ out_dist,
                 float* __restrict__ out, int write_loss) {
    __shared__ float red[8][11];
    __shared__ int s_last;
    const int q = blockIdx.x;
    const int tid = threadIdx.x;
    const int wid = tid >> 5;

    const float4* h0 = reinterpret_cast<const float4*>(&g_qph[0][(size_t)q * ND]);
    const float4* h1 = reinterpret_cast<const float4*>(&g_qph[1][(size_t)q * ND]);
    float4 acc0 = f4add(h0[tid],       h1[tid]);
    float4 acc1 = f4add(h0[tid + 256], h1[tid + 256]);

    // 11 block reductions: 5 dot(q,s), 5 ||s||^2 (redundant, L2-cheap), 1 ||q||^2
    float part[11];
    part[10] = f4dot(acc0, acc0) + f4dot(acc1, acc1);
    #pragma unroll
    for (int s = 0; s < NS; s++) {
        const float4* s0 = reinterpret_cast<const float4*>(&g_sph[0][(size_t)s * ND]);
        const float4* s1 = reinterpret_cast<const float4*>(&g_sph[1][(size_t)s * ND]);
        float4 sp0 = f4add(__ldg(&s0[tid]),       __ldg(&s1[tid]));
        float4 sp1 = f4add(__ldg(&s0[tid + 256]), __ldg(&s1[tid + 256]));
        part[s]     = f4dot(acc0, sp0) + f4dot(acc1, sp1);
        part[5 + s] = f4dot(sp0, sp0) + f4dot(sp1, sp1);
    }
    #pragma unroll
    for (int j = 0; j < 11; j++) {
        float v = warp_sum(part[j]);
        if ((tid & 31) == 0) red[wid][j] = v;
    }
    __syncthreads();

    if (tid == 0) {
        float tot[11];
        #pragma unroll
        for (int j = 0; j < 11; j++) {
            float t2 = 0.f;
            #pragma unroll
            for (int w = 0; w < 8; w++) t2 += red[w][j];
            tot[j] = t2;
        }
        const float qn = sqrtf(tot[10]);
        #pragma unroll
        for (int s = 0; s < NS; s++) {
            float denom = fmaxf(qn * sqrtf(tot[5 + s]), EPS);
            float d = tot[s] / denom;
            g_dist[q * NS + s] = d;
            out_dist[q * NS + s] = 1.0f - d;
        }
    }

    // ── last-block loss epilogue ──
    __threadfence();                       // publish g_dist
    __syncthreads();
    if (tid == 0) {
        s_last = (atomicAdd(&g_done, 1) == NQ - 1);
    }
    __syncthreads();
    if (!s_last) return;
    __threadfence();                       // acquire all blocks' g_dist

    // Parallel int64-vs-int32 label detect: values < 5, so for int64 (LE)
    // every odd 32-bit word among the first 512 words is a zero high-half.
    const int is64 = __syncthreads_and(ys32[2 * tid + 1] == 0);

    // 256 threads x 2 queries each
    float nlp = 0.f;
    #pragma unroll
    for (int r = 0; r < 2; r++) {
        const int i = tid + r * 256;
        const int y = is64 ? ys32[2 * i] : ys32[i];
        float d[NS];
        #pragma unroll
        for (int s = 0; s < NS; s++) d[s] = g_dist[i * NS + s];
        float m = d[0];
        #pragma unroll
        for (int s = 1; s < NS; s++) m = fmaxf(m, d[s]);
        float se = 0.f;
        #pragma unroll
        for (int s = 0; s < NS; s++) se += __expf(d[s] - m);
        nlp += -(d[y] - (m + logf(se)));
    }
    nlp = warp_sum(nlp);
    __shared__ float lred[8];
    if ((tid & 31) == 0) lred[wid] = nlp;
    __syncthreads();
    if (tid == 0) {
        float tot = 0.f;
        #pragma unroll
        for (int w = 0; w < 8; w++) tot += lred[w];
        if (write_loss) out[0] = tot * (1.0f / (float)NQ);
        g_done = 0;                        // reset for next graph replay
    }
}

extern "C" void kernel_launch(void* const* d_in, const int* in_sizes, int n_in,
                              void* d_out, int out_size) {
    const float* supp  = (const float*)d_in[0];
    const float* query = (const float*)d_in[1];
    const int*   ys    = (const int*)d_in[2];
    if (n_in >= 2 && in_sizes[0] > in_sizes[1]) {
        const float* t = supp; supp = query; query = t;
    }
    float* out = (float*)d_out;

    const int dist_off = (out_size > NQ * NS) ? (out_size - NQ * NS) : 0;
    const int write_loss = (out_size > NQ * NS) ? 1 : 0;

    pool_all_kernel<<<2 * NS + 2 * NQ, 256>>>(supp, query);
    dist_loss_kernel<<<NQ, 256>>>(ys, out + dist_off, out, write_loss);
}

// round 7
// speedup vs baseline: 1.0346x; 1.0046x over previous
#include <cuda_runtime.h>
#include <math.h>

// Problem shape (fixed by the reference setup_inputs)
#define NS 5        // S: num support classes
#define NQ 512      // Q: num queries
#define NT 64       // T: tokens pooled (mean)
#define NTH (NT/2)  // half split for pooling
#define ND 2048     // D: feature dim
#define ND4 (ND/4)  // 512 float4 per row
#define EPS 1e-8f

// Scratch (no allocations allowed in kernel_launch)
__device__ float g_sph[2][NS * ND];   // per-half raw support sums
__device__ float g_sp[NS * ND];       // combined support sums
__device__ float g_sn[NS];            // support norms (of raw sums)
__device__ float g_qph[2][NQ * ND];   // per-half raw query sums
__device__ float g_dist[NQ * NS];     // cosine sim [Q, S]
__device__ int   g_pair_s[NS] = {0};  // supp half-pair arrival counters
__device__ int   g_sdone = 0;         // combined supp rows done (0..NS)
__device__ int   g_qcnt[NQ] = {0};    // query half-pair arrival counters
__device__ int   g_done = 0;          // finished dist rows (0..NQ)

__device__ __forceinline__ float4 f4add(float4 a, float4 b) {
    a.x += b.x; a.y += b.y; a.z += b.z; a.w += b.w; return a;
}
__device__ __forceinline__ float f4dot(float4 a, float4 b) {
    return a.x * b.x + a.y * b.y + a.z * b.z + a.w * b.w;
}
__device__ __forceinline__ float warp_sum(float v) {
    #pragma unroll
    for (int o = 16; o > 0; o >>= 1) v += __shfl_xor_sync(0xffffffffu, v, o);
    return v;
}

// ─── ONE fused kernel: stream-pool + dist + loss, single launch ────────────
// grid = 2*NS + 2*NQ = 1034 blocks, block = 256; single resident wave.
// All CTAs pool a uniform 32x2048 half-slab (256 KB) of raw sums (cosine sim
// is scale-invariant -> no 1/NT anywhere; EPS clamp inactive either way).
//  - supp half pair: 2nd arriver combines -> g_sp, norm -> g_sn, bumps g_sdone
//  - query half pair: 2nd arriver waits g_sdone==NS (long satisfied), combines
//    halves, computes 6 block reductions, writes dist row, bumps g_done
//  - 512th dist finisher computes the CE loss and resets all counters
__global__ void __launch_bounds__(256, 8)
fused_kernel(const float* __restrict__ supp,
             const float* __restrict__ query,
             const int* __restrict__ ys32,
             float* __restrict__ out_dist,
             float* __restrict__ out, int write_loss) {
    const int bid = blockIdx.x;
    const int tid = threadIdx.x;
    const int wid = tid >> 5;
    const bool is_supp = (bid < 2 * NS);

    int q = 0, half, s = 0;
    const float* src;
    float* dst;
    if (is_supp) {
        s = bid >> 1; half = bid & 1;
        src = supp + ((size_t)s * NT + (size_t)half * NTH) * ND;
        dst = &g_sph[half][(size_t)s * ND];
    } else {
        const int i = bid - 2 * NS;
        q = i >> 1; half = i & 1;
        src = query + ((size_t)q * NT + (size_t)half * NTH) * ND;
        dst = &g_qph[half][(size_t)q * ND];
    }

    // ── streaming half-pool: 32 rows x 8 KB, coalesced float4 ──
    const float4* base = reinterpret_cast<const float4*>(src);
    float4 acc0 = make_float4(0.f, 0.f, 0.f, 0.f);
    float4 acc1 = make_float4(0.f, 0.f, 0.f, 0.f);
    #pragma unroll 8
    for (int t = 0; t < NTH; t++) {
        const float4* row = base + (size_t)t * ND4;
        acc0 = f4add(acc0, row[tid]);
        acc1 = f4add(acc1, row[tid + 256]);
    }
    float4* d4 = reinterpret_cast<float4*>(dst);
    d4[tid] = acc0;
    d4[tid + 256] = acc1;

    // publish-then-signal: syncthreads orders all block writes, tid0 fences
    __syncthreads();
    __shared__ int s_old;
    if (tid == 0) {
        __threadfence();
        s_old = atomicAdd(is_supp ? &g_pair_s[s] : &g_qcnt[q], 1);
    }
    __syncthreads();
    if (s_old == 0) return;          // first arriver of the pair exits
    if (tid == 0) __threadfence();   // acquire partner's half
    __syncthreads();

    if (is_supp) {
        // ── supp combiner: g_sp[s] = h0+h1, g_sn[s] = ||.|| ──
        const float4* p4 =
            reinterpret_cast<const float4*>(&g_sph[half ^ 1][(size_t)s * ND]);
        acc0 = f4add(acc0, p4[tid]);
        acc1 = f4add(acc1, p4[tid + 256]);
        float4* sp4 = reinterpret_cast<float4*>(&g_sp[(size_t)s * ND]);
        sp4[tid] = acc0;
        sp4[tid + 256] = acc1;
        float p = f4dot(acc0, acc0) + f4dot(acc1, acc1);
        p = warp_sum(p);
        __shared__ float sred[8];
        if ((tid & 31) == 0) sred[wid] = p;
        __syncthreads();
        if (tid == 0) {
            float tot = 0.f;
            #pragma unroll
            for (int w = 0; w < 8; w++) tot += sred[w];
            g_sn[s] = sqrtf(tot);
            __threadfence();
            atomicAdd(&g_sdone, 1);
        }
        return;
    }

    // ── query finisher: combine halves, dist row ──
    const float4* p4 =
        reinterpret_cast<const float4*>(&g_qph[half ^ 1][(size_t)q * ND]);
    acc0 = f4add(acc0, p4[tid]);
    acc1 = f4add(acc1, p4[tid + 256]);

    if (tid == 0) {  // supp combiners finish ~20us before any query finisher
        while (*(volatile int*)&g_sdone < NS) { }
        __threadfence();
    }
    __syncthreads();

    float part[6];
    part[5] = f4dot(acc0, acc0) + f4dot(acc1, acc1);
    #pragma unroll
    for (int j = 0; j < NS; j++) {
        const float4* sp4 =
            reinterpret_cast<const float4*>(&g_sp[(size_t)j * ND]);
        part[j] = f4dot(acc0, __ldg(&sp4[tid])) +
                  f4dot(acc1, __ldg(&sp4[tid + 256]));
    }
    __shared__ float red[8][6];
    #pragma unroll
    for (int j = 0; j < 6; j++) {
        float v = warp_sum(part[j]);
        if ((tid & 31) == 0) red[wid][j] = v;
    }
    __syncthreads();

    __shared__ int s_last;
    if (tid == 0) {
        float tot[6];
        #pragma unroll
        for (int j = 0; j < 6; j++) {
            float t2 = 0.f;
            #pragma unroll
            for (int w = 0; w < 8; w++) t2 += red[w][j];
            tot[j] = t2;
        }
        const float qn = sqrtf(tot[5]);
        #pragma unroll
        for (int j = 0; j < NS; j++) {
            float denom = fmaxf(qn * g_sn[j], EPS);
            float d = tot[j] / denom;
            g_dist[q * NS + j] = d;
            out_dist[q * NS + j] = 1.0f - d;
        }
        __threadfence();
        s_last = (atomicAdd(&g_done, 1) == NQ - 1);
    }
    __syncthreads();
    if (!s_last) return;
    if (tid == 0) __threadfence();
    __syncthreads();

    // ── loss epilogue (one block, all of g_dist L2-resident) ──
    // Parallel int64-vs-int32 detect: labels < 5, so int64 high words are 0.
    const int is64 = __syncthreads_and(ys32[2 * tid + 1] == 0);

    float nlp = 0.f;
    #pragma unroll
    for (int r = 0; r < 2; r++) {
        const int i = tid + r * 256;
        const int y = is64 ? ys32[2 * i] : ys32[i];
        float d[NS];
        #pragma unroll
        for (int j = 0; j < NS; j++) d[j] = g_dist[i * NS + j];
        float m = d[0];
        #pragma unroll
        for (int j = 1; j < NS; j++) m = fmaxf(m, d[j]);
        float se = 0.f;
        #pragma unroll
        for (int j = 0; j < NS; j++) se += __expf(d[j] - m);
        nlp += -(d[y] - (m + logf(se)));
    }
    nlp = warp_sum(nlp);
    __shared__ float lred[8];
    if ((tid & 31) == 0) lred[wid] = nlp;
    __syncthreads();

    // reset counters for the next graph replay (all pair uses are complete:
    // every finisher incremented g_done after its last counter access)
    if (tid < NS) g_pair_s[tid] = 0;
    g_qcnt[tid] = 0;
    g_qcnt[tid + 256] = 0;
    if (tid == 0) {
        g_sdone = 0;
        g_done = 0;
        float tot = 0.f;
        #pragma unroll
        for (int w = 0; w < 8; w++) tot += lred[w];
        if (write_loss) out[0] = tot * (1.0f / (float)NQ);
    }
}

extern "C" void kernel_launch(void* const* d_in, const int* in_sizes, int n_in,
                              void* d_out, int out_size) {
    const float* supp  = (const float*)d_in[0];
    const float* query = (const float*)d_in[1];
    const int*   ys    = (const int*)d_in[2];
    if (n_in >= 2 && in_sizes[0] > in_sizes[1]) {
        const float* t = supp; supp = query; query = t;
    }
    float* out = (float*)d_out;

    const int dist_off = (out_size > NQ * NS) ? (out_size - NQ * NS) : 0;
    const int write_loss = (out_size > NQ * NS) ? 1 : 0;

    fused_kernel<<<2 * NS + 2 * NQ, 256>>>(supp, query, ys,
                                           out + dist_off, out, write_loss);
}

// round 8
// speedup vs baseline: 1.1356x; 1.0976x over previous
#include <cuda_runtime.h>
#include <math.h>

// Problem shape (fixed by the reference setup_inputs)
#define NS 5        // S: num support classes
#define NQ 512      // Q: num queries
#define NT 64       // T: tokens pooled (mean)
#define NTH (NT/2)  // half split for SUPP pooling only
#define ND 2048     // D: feature dim
#define ND4 (ND/4)  // 512 float4 per row
#define EPS 1e-8f

// Scratch (no allocations allowed in kernel_launch)
__device__ float g_sph[2][NS * ND];   // per-half raw support sums
__device__ float g_sp[NS * ND];       // combined support sums
__device__ float g_sn[NS];            // support norms (of raw sums)
__device__ float g_dist[NQ * NS];     // cosine sim [Q, S]
__device__ int   g_pair_s[NS] = {0};  // supp half-pair arrival counters
__device__ int   g_sdone = 0;         // combined supp rows done (0..NS)
__device__ int   g_done = 0;          // finished dist rows (0..NQ)

__device__ __forceinline__ float4 f4add(float4 a, float4 b) {
    a.x += b.x; a.y += b.y; a.z += b.z; a.w += b.w; return a;
}
__device__ __forceinline__ float f4dot(float4 a, float4 b) {
    return a.x * b.x + a.y * b.y + a.z * b.z + a.w * b.w;
}
__device__ __forceinline__ float warp_sum(float v) {
    #pragma unroll
    for (int o = 16; o > 0; o >>= 1) v += __shfl_xor_sync(0xffffffffu, v, o);
    return v;
}

// ─── ONE fused kernel, single launch ───────────────────────────────────────
// grid = NQ + 2*NS = 522 blocks, block = 256.
//  bid < NQ : pool FULL query q (64 rows, 512 KB) into registers, then spin
//             on g_sdone (pre-satisfied: supp CTAs stream half the bytes and
//             finish mid-wave), dot vs g_sp, write dist row. No query scratch.
//  bid >= NQ: supp half (32 rows, 256 KB); 2nd arriver of the pair combines
//             -> g_sp, norm -> g_sn, bumps g_sdone.
//  512th dist finisher computes the CE loss and resets all counters.
// Cosine sim is scale-invariant -> raw sums, no 1/NT anywhere.
__global__ void __launch_bounds__(256, 8)
fused_kernel(const float* __restrict__ supp,
             const float* __restrict__ query,
             const int* __restrict__ ys32,
             float* __restrict__ out_dist,
             float* __restrict__ out, int write_loss) {
    const int bid = blockIdx.x;
    const int tid = threadIdx.x;
    const int wid = tid >> 5;

    if (bid >= NQ) {
        // ── supp half-pool ──
        const int i = bid - NQ;
        const int s = i >> 1, half = i & 1;
        const float4* base = reinterpret_cast<const float4*>(
            supp + ((size_t)s * NT + (size_t)half * NTH) * ND);
        float4 acc0 = make_float4(0.f, 0.f, 0.f, 0.f);
        float4 acc1 = make_float4(0.f, 0.f, 0.f, 0.f);
        #pragma unroll 8
        for (int t = 0; t < NTH; t++) {
            const float4* row = base + (size_t)t * ND4;
            acc0 = f4add(acc0, row[tid]);
            acc1 = f4add(acc1, row[tid + 256]);
        }
        float4* d4 = reinterpret_cast<float4*>(&g_sph[half][(size_t)s * ND]);
        d4[tid] = acc0;
        d4[tid + 256] = acc1;

        __syncthreads();
        __shared__ int s_old;
        if (tid == 0) {
            __threadfence();
            s_old = atomicAdd(&g_pair_s[s], 1);
        }
        __syncthreads();
        if (s_old == 0) return;          // first arriver exits
        if (tid == 0) __threadfence();   // acquire partner half
        __syncthreads();

        const float4* p4 =
            reinterpret_cast<const float4*>(&g_sph[half ^ 1][(size_t)s * ND]);
        acc0 = f4add(acc0, p4[tid]);
        acc1 = f4add(acc1, p4[tid + 256]);
        float4* sp4 = reinterpret_cast<float4*>(&g_sp[(size_t)s * ND]);
        sp4[tid] = acc0;
        sp4[tid + 256] = acc1;
        float p = f4dot(acc0, acc0) + f4dot(acc1, acc1);
        p = warp_sum(p);
        __shared__ float sred[8];
        if ((tid & 31) == 0) sred[wid] = p;
        __syncthreads();
        if (tid == 0) {
            float tot = 0.f;
            #pragma unroll
            for (int w = 0; w < 8; w++) tot += sred[w];
            g_sn[s] = sqrtf(tot);
            __threadfence();
            atomicAdd(&g_sdone, 1);
        }
        return;
    }

    // ── query CTA: full 64-row pool, all in registers ──
    const int q = bid;
    const float4* base =
        reinterpret_cast<const float4*>(query + (size_t)q * NT * ND);
    float4 acc0 = make_float4(0.f, 0.f, 0.f, 0.f);
    float4 acc1 = make_float4(0.f, 0.f, 0.f, 0.f);
    #pragma unroll 8
    for (int t = 0; t < NT; t++) {
        const float4* row = base + (size_t)t * ND4;
        acc0 = f4add(acc0, row[tid]);
        acc1 = f4add(acc1, row[tid + 256]);
    }

    // supp combiners streamed half the bytes -> long done; spin is free
    if (tid == 0) {
        while (*(volatile int*)&g_sdone < NS) { }
        __threadfence();
    }
    __syncthreads();

    // 6 block reductions: 5 dot(q,s) + ||q||^2; 40 KB L2 read per CTA
    float part[6];
    part[5] = f4dot(acc0, acc0) + f4dot(acc1, acc1);
    #pragma unroll
    for (int j = 0; j < NS; j++) {
        const float4* sp4 =
            reinterpret_cast<const float4*>(&g_sp[(size_t)j * ND]);
        part[j] = f4dot(acc0, __ldg(&sp4[tid])) +
                  f4dot(acc1, __ldg(&sp4[tid + 256]));
    }
    __shared__ float red[8][6];
    #pragma unroll
    for (int j = 0; j < 6; j++) {
        float v = warp_sum(part[j]);
        if ((tid & 31) == 0) red[wid][j] = v;
    }
    __syncthreads();

    __shared__ int s_last;
    if (tid == 0) {
        float tot[6];
        #pragma unroll
        for (int j = 0; j < 6; j++) {
            float t2 = 0.f;
            #pragma unroll
            for (int w = 0; w < 8; w++) t2 += red[w][j];
            tot[j] = t2;
        }
        const float qn = sqrtf(tot[5]);
        #pragma unroll
        for (int j = 0; j < NS; j++) {
            float denom = fmaxf(qn * g_sn[j], EPS);
            float d = tot[j] / denom;
            g_dist[q * NS + j] = d;
            out_dist[q * NS + j] = 1.0f - d;
        }
        __threadfence();
        s_last = (atomicAdd(&g_done, 1) == NQ - 1);
    }
    __syncthreads();
    if (!s_last) return;
    if (tid == 0) __threadfence();
    __syncthreads();

    // ── loss epilogue (one block; g_dist is L2-resident) ──
    // Parallel int64-vs-int32 detect: labels < 5, so int64 high words are 0.
    const int is64 = __syncthreads_and(ys32[2 * tid + 1] == 0);

    float nlp = 0.f;
    #pragma unroll
    for (int r = 0; r < 2; r++) {
        const int i = tid + r * 256;
        const int y = is64 ? ys32[2 * i] : ys32[i];
        float d[NS];
        #pragma unroll
        for (int j = 0; j < NS; j++) d[j] = g_dist[i * NS + j];
        float m = d[0];
        #pragma unroll
        for (int j = 1; j < NS; j++) m = fmaxf(m, d[j]);
        float se = 0.f;
        #pragma unroll
        for (int j = 0; j < NS; j++) se += __expf(d[j] - m);
        nlp += -(d[y] - (m + logf(se)));
    }
    nlp = warp_sum(nlp);
    __shared__ float lred[8];
    if ((tid & 31) == 0) lred[wid] = nlp;
    __syncthreads();

    // reset counters for next graph replay (all uses complete by now)
    if (tid < NS) g_pair_s[tid] = 0;
    if (tid == 0) {
        g_sdone = 0;
        g_done = 0;
        float tot = 0.f;
        #pragma unroll
        for (int w = 0; w < 8; w++) tot += lred[w];
        if (write_loss) out[0] = tot * (1.0f / (float)NQ);
    }
}

extern "C" void kernel_launch(void* const* d_in, const int* in_sizes, int n_in,
                              void* d_out, int out_size) {
    const float* supp  = (const float*)d_in[0];
    const float* query = (const float*)d_in[1];
    const int*   ys    = (const int*)d_in[2];
    if (n_in >= 2 && in_sizes[0] > in_sizes[1]) {
        const float* t = supp; supp = query; query = t;
    }
    float* out = (float*)d_out;

    const int dist_off = (out_size > NQ * NS) ? (out_size - NQ * NS) : 0;
    const int write_loss = (out_size > NQ * NS) ? 1 : 0;

    fused_kernel<<<NQ + 2 * NS, 256>>>(supp, query, ys,
                                       out + dist_off, out, write_loss);
}

// round 10
// speedup vs baseline: 1.1599x; 1.0214x over previous
#include <cuda_runtime.h>
#include <math.h>

// Problem shape (fixed by the reference setup_inputs)
#define NS 5        // S: num support classes
#define NQ 512      // Q: num queries
#define NT 64       // T: tokens pooled (mean)
#define NTH (NT/2)  // half split for SUPP pooling only
#define ND 2048     // D: feature dim
#define ND4 (ND/4)  // 512 float4 per row == threads per block
#define EPS 1e-8f

// Scratch (no allocations allowed in kernel_launch)
__device__ float g_sph[2][NS * ND];   // per-half raw support sums
__device__ float g_sp[NS * ND];       // combined support sums
__device__ float g_sn[NS];            // support norms (of raw sums)
__device__ float g_dist[NQ * NS];     // cosine sim [Q, S]
__device__ int   g_pair_s[NS] = {0};  // supp half-pair arrival counters
__device__ int   g_sdone = 0;         // combined supp rows done (0..NS)
__device__ int   g_done = 0;          // finished dist rows (0..NQ)

__device__ __forceinline__ float4 f4add(float4 a, float4 b) {
    a.x += b.x; a.y += b.y; a.z += b.z; a.w += b.w; return a;
}
__device__ __forceinline__ float f4dot(float4 a, float4 b) {
    return a.x * b.x + a.y * b.y + a.z * b.z + a.w * b.w;
}
__device__ __forceinline__ float warp_sum(float v) {
    #pragma unroll
    for (int o = 16; o > 0; o >>= 1) v += __shfl_xor_sync(0xffffffffu, v, o);
    return v;
}

// ─── ONE fused kernel, single launch ───────────────────────────────────────
// grid = NQ + 2*NS = 522 blocks, block = 512 (one thread per float4 column).
//  bid < NQ : pool FULL query q (64 rows, 512 KB) into ONE register float4,
//             spin g_sdone (pre-satisfied), dot vs g_sp, write dist row.
//  bid >= NQ: supp half (32 rows, 256 KB); 2nd pair arriver combines -> g_sp,
//             norm -> g_sn, bumps g_sdone (done mid-wave: half the bytes).
//  512th dist finisher computes the CE loss and resets all counters.
// Cosine sim is scale-invariant -> raw sums, no 1/NT anywhere.
__global__ void __launch_bounds__(512, 4)
fused_kernel(const float* __restrict__ supp,
             const float* __restrict__ query,
             const int* __restrict__ ys32,
             float* __restrict__ out_dist,
             float* __restrict__ out, int write_loss) {
    const int bid = blockIdx.x;
    const int tid = threadIdx.x;
    const int wid = tid >> 5;

    if (bid >= NQ) {
        // ── supp half-pool (32 rows) ──
        const int i = bid - NQ;
        const int s = i >> 1, half = i & 1;
        const float4* base = reinterpret_cast<const float4*>(
            supp + ((size_t)s * NT + (size_t)half * NTH) * ND);
        float4 acc = make_float4(0.f, 0.f, 0.f, 0.f);
        #pragma unroll 8
        for (int t = 0; t < NTH; t++)
            acc = f4add(acc, base[(size_t)t * ND4 + tid]);
        reinterpret_cast<float4*>(&g_sph[half][(size_t)s * ND])[tid] = acc;

        __syncthreads();
        __shared__ int s_old;
        if (tid == 0) {
            __threadfence();
            s_old = atomicAdd(&g_pair_s[s], 1);
        }
        __syncthreads();
        if (s_old == 0) return;          // first arriver exits
        if (tid == 0) __threadfence();   // acquire partner half
        __syncthreads();

        acc = f4add(acc, reinterpret_cast<const float4*>(
                             &g_sph[half ^ 1][(size_t)s * ND])[tid]);
        reinterpret_cast<float4*>(&g_sp[(size_t)s * ND])[tid] = acc;
        float p = warp_sum(f4dot(acc, acc));
        __shared__ float sred[16];
        if ((tid & 31) == 0) sred[wid] = p;
        __syncthreads();
        if (tid == 0) {
            float tot = 0.f;
            #pragma unroll
            for (int w = 0; w < 16; w++) tot += sred[w];
            g_sn[s] = sqrtf(tot);
            __threadfence();
            atomicAdd(&g_sdone, 1);
        }
        return;
    }

    // ── query CTA: full 64-row pool into one register float4 ──
    const int q = bid;
    const float4* base =
        reinterpret_cast<const float4*>(query + (size_t)q * NT * ND);
    float4 acc = make_float4(0.f, 0.f, 0.f, 0.f);
    #pragma unroll 8
    for (int t = 0; t < NT; t++)
        acc = f4add(acc, base[(size_t)t * ND4 + tid]);

    // supp combiners stream half the bytes -> long done; spin is free
    if (tid == 0) {
        while (*(volatile int*)&g_sdone < NS) { }
        __threadfence();
    }
    __syncthreads();

    // 6 block reductions: 5 dot(q,s) + ||q||^2; 40 KB L2 read per CTA
    float part[6];
    part[5] = f4dot(acc, acc);
    #pragma unroll
    for (int j = 0; j < NS; j++)
        part[j] = f4dot(acc, __ldg(&reinterpret_cast<const float4*>(
                                        &g_sp[(size_t)j * ND])[tid]));
    __shared__ float red[16][6];
    #pragma unroll
    for (int j = 0; j < 6; j++) {
        float v = warp_sum(part[j]);
        if ((tid & 31) == 0) red[wid][j] = v;
    }
    __syncthreads();

    __shared__ int s_last;
    if (tid == 0) {
        float tot[6];
        #pragma unroll
        for (int j = 0; j < 6; j++) {
            float t2 = 0.f;
            #pragma unroll
            for (int w = 0; w < 16; w++) t2 += red[w][j];
            tot[j] = t2;
        }
        const float qn = sqrtf(tot[5]);
        #pragma unroll
        for (int j = 0; j < NS; j++) {
            float denom = fmaxf(qn * g_sn[j], EPS);
            float d = tot[j] / denom;
            g_dist[q * NS + j] = d;
            out_dist[q * NS + j] = 1.0f - d;
        }
        __threadfence();
        s_last = (atomicAdd(&g_done, 1) == NQ - 1);
    }
    __syncthreads();
    if (!s_last) return;
    if (tid == 0) __threadfence();
    __syncthreads();

    // ── loss epilogue (one block, 512 threads = one query each) ──
    // Parallel int64-vs-int32 detect: labels < 5, so int64 high words are 0.
    const int is64 = __syncthreads_and(ys32[2 * tid + 1] == 0);

    const int y = is64 ? ys32[2 * tid] : ys32[tid];
    float d[NS];
    #pragma unroll
    for (int j = 0; j < NS; j++) d[j] = g_dist[tid * NS + j];
    float m = d[0];
    #pragma unroll
    for (int j = 1; j < NS; j++) m = fmaxf(m, d[j]);
    float se = 0.f;
    #pragma unroll
    for (int j = 0; j < NS; j++) se += __expf(d[j] - m);
    float nlp = -(d[y] - (m + logf(se)));

    nlp = warp_sum(nlp);
    __shared__ float lred[16];
    if ((tid & 31) == 0) lred[wid] = nlp;
    __syncthreads();

    // reset counters for next graph replay (all uses complete by now)
    if (tid < NS) g_pair_s[tid] = 0;
    if (tid == 0) {
        g_sdone = 0;
        g_done = 0;
        float tot = 0.f;
        #pragma unroll
        for (int w = 0; w < 16; w++) tot += lred[w];
        if (write_loss) out[0] = tot * (1.0f / (float)NQ);
    }
}

extern "C" void kernel_launch(void* const* d_in, const int* in_sizes, int n_in,
                              void* d_out, int out_size) {
    const float* supp  = (const float*)d_in[0];
    const float* query = (const float*)d_in[1];
    const int*   ys    = (const int*)d_in[2];
    if (n_in >= 2 && in_sizes[0] > in_sizes[1]) {
        const float* t = supp; supp = query; query = t;
    }
    float* out = (float*)d_out;

    const int dist_off = (out_size > NQ * NS) ? (out_size - NQ * NS) : 0;
    const int write_loss = (out_size > NQ * NS) ? 1 : 0;

    fused_kernel<<<NQ + 2 * NS, 512>>>(supp, query, ys,
                                       out + dist_off, out, write_loss);
}